// round 15
// baseline (speedup 1.0000x reference)
#include <cuda_runtime.h>

// Problem constants
#define Bq      128
#define Tq      1024
#define IN_DIM  17
#define Hq      512
#define OUT_DIM 17

// Partition: L0 blocks own NU0=12 units (G=48 cols, K=512+17 fused),
//            L1 blocks own NU1=6 units (G=24 cols, K=1024 fused).
#define NU0  12
#define NU1  6
#define NB0  43
#define NB1  86
#define NBLK (NB0 + NB1)      // 129 blocks <= 148 SMs, all co-resident

#define KC       64
#define THREADS  416          // 12 compute warps + warp 12 (DMA lane 0 = tid 384)

// smem: Hbuf[2][64*128]f32 (64KB) | mbar (64B) | Wbuf[2][64*48]u64 (48KB)
#define HS_BYTES       (2*KC*Bq*4)            // 65536
#define SMEM_MBAR_OFF  HS_BYTES
#define SMEM_WS_OFF    (HS_BYTES + 64)        // 65600
#define WS_BYTES       (2*KC*48*8)            // 49152
#define SMEM_BYTES     (SMEM_WS_OFF + WS_BYTES)   // 114752

typedef unsigned long long u64;

// ---------------- persistent device state ----------------
__device__ __align__(128) float g_h0[2][Hq * Bq];
__device__ __align__(128) float g_h1[2][Hq * Bq];
__device__ __align__(128) float g_c0[Hq * Bq];
__device__ __align__(128) float g_c1[Hq * Bq];
// x transposed [t][i][b], + one zero pad row so chunk 8 can stage 18 rows
__device__ __align__(128) float g_xT[(Tq * IN_DIM + 1) * Bq];
__device__ float g_bias0[4 * Hq];
__device__ float g_bias1[4 * Hq];

// Pre-duplicated f32x2 weights, per-block contiguous, chunked [c][k][col]:
//  L0: 8 chunks x (64*48) + x-chunk 18*48 (rows 17 zero)   = 25440 u64/block
//  L1: wi,wh each 8 chunks x (64*24)                       = 12288 u64/block
#define W0_CH   (KC*48)          // 3072
#define W0_SZ   (8*W0_CH)        // 24576
#define WX_SZ   (18*48)          // 864
#define W1_CH   (KC*24)          // 1536
#define W1_SZ   (8*W1_CH)        // 12288
__device__ __align__(16) u64 g_w0p[(size_t)NB0 * W0_SZ];
__device__ __align__(16) u64 g_wxp[(size_t)NB0 * WX_SZ];
__device__ __align__(16) u64 g_w1i[(size_t)NB1 * W1_SZ];
__device__ __align__(16) u64 g_w1h[(size_t)NB1 * W1_SZ];

// Grid barrier (sense reversal)
__device__ unsigned g_bar_count = 0;
__device__ volatile unsigned g_bar_gen = 0;

__device__ __forceinline__ void grid_barrier() {
    __syncthreads();
    if (threadIdx.x == 0) {
        unsigned gen = g_bar_gen;
        __threadfence();
        if (atomicAdd(&g_bar_count, 1) == NBLK - 1) {
            g_bar_count = 0;
            __threadfence();
            g_bar_gen = gen + 1;
        } else {
            while (g_bar_gen == gen) __nanosleep(64);
        }
    }
    __syncthreads();
}

__device__ __forceinline__ void fma2(u64 &a, u64 x, u64 y) {
    asm("fma.rn.f32x2 %0, %1, %2, %0;" : "+l"(a) : "l"(x), "l"(y));
}
__device__ __forceinline__ u64 pack2(float w) {
    u64 r; asm("mov.b64 %0, {%1, %1};" : "=l"(r) : "f"(w)); return r;
}

// ---------------- mbarrier + bulk-copy primitives ----------------
__device__ __forceinline__ void mbar_init(unsigned mbar, unsigned count) {
    asm volatile("mbarrier.init.shared.b64 [%0], %1;" :: "r"(mbar), "r"(count) : "memory");
}
__device__ __forceinline__ void mbar_expect(unsigned mbar, unsigned bytes) {
    asm volatile("mbarrier.arrive.expect_tx.shared.b64 _, [%0], %1;"
                 :: "r"(mbar), "r"(bytes) : "memory");
}
__device__ __forceinline__ void bulk_g2s(unsigned dst, const void* src,
                                         unsigned bytes, unsigned mbar) {
    asm volatile("cp.async.bulk.shared::cta.global.mbarrier::complete_tx::bytes "
                 "[%0], [%1], %2, [%3];"
                 :: "r"(dst), "l"(src), "r"(bytes), "r"(mbar) : "memory");
}
__device__ __forceinline__ void mbar_wait(unsigned mbar, unsigned phase) {
    asm volatile(
        "{\n\t.reg .pred P;\n\t"
        "WAIT_%=:\n\t"
        "mbarrier.try_wait.parity.acquire.cta.shared::cta.b64 P, [%0], %1, 0x989680;\n\t"
        "@P bra DONE_%=;\n\t"
        "bra WAIT_%=;\n\t"
        "DONE_%=:\n\t}"
        :: "r"(mbar), "r"(phase) : "memory");
}

// ---------------- inner GEMM loops ----------------
// L0: lane tile 4b x 8c. hp pre-offset by batch, wp by col (stride 48 u64/k).
__device__ __forceinline__ void l0_inner(const float* __restrict__ hp,
                                         const u64* __restrict__ wp,
                                         int kbeg, int kend, u64 (&acc)[8][2])
{
    #pragma unroll 8
    for (int k = kbeg; k < kend; ++k) {
        ulonglong2 h = *(const ulonglong2*)(hp + k * Bq);
        const u64* w = wp + k * 48;
        ulonglong2 wA = *(const ulonglong2*)(w);
        ulonglong2 wB = *(const ulonglong2*)(w + 2);
        ulonglong2 wC = *(const ulonglong2*)(w + 4);
        ulonglong2 wD = *(const ulonglong2*)(w + 6);
        fma2(acc[0][0], h.x, wA.x); fma2(acc[0][1], h.y, wA.x);
        fma2(acc[1][0], h.x, wA.y); fma2(acc[1][1], h.y, wA.y);
        fma2(acc[2][0], h.x, wB.x); fma2(acc[2][1], h.y, wB.x);
        fma2(acc[3][0], h.x, wB.y); fma2(acc[3][1], h.y, wB.y);
        fma2(acc[4][0], h.x, wC.x); fma2(acc[4][1], h.y, wC.x);
        fma2(acc[5][0], h.x, wC.y); fma2(acc[5][1], h.y, wC.y);
        fma2(acc[6][0], h.x, wD.x); fma2(acc[6][1], h.y, wD.x);
        fma2(acc[7][0], h.x, wD.y); fma2(acc[7][1], h.y, wD.y);
    }
}
// L1: lane tile 4b x 4c (stride 24 u64/k).
__device__ __forceinline__ void l1_inner(const float* __restrict__ hp,
                                         const u64* __restrict__ wp,
                                         int kbeg, int kend, u64 (&acc)[4][2])
{
    #pragma unroll 8
    for (int k = kbeg; k < kend; ++k) {
        ulonglong2 h = *(const ulonglong2*)(hp + k * Bq);
        const u64* w = wp + k * 24;
        ulonglong2 wA = *(const ulonglong2*)(w);
        ulonglong2 wB = *(const ulonglong2*)(w + 2);
        fma2(acc[0][0], h.x, wA.x); fma2(acc[0][1], h.y, wA.x);
        fma2(acc[1][0], h.x, wA.y); fma2(acc[1][1], h.y, wA.y);
        fma2(acc[2][0], h.x, wB.x); fma2(acc[2][1], h.y, wB.x);
        fma2(acc[3][0], h.x, wB.y); fma2(acc[3][1], h.y, wB.y);
    }
}

// ---------------- LSTM cell math ----------------
__device__ __forceinline__ void cell(float gi, float gf, float gg, float go,
                                     float* __restrict__ cbuf,
                                     float* __restrict__ hdst, int off)
{
    float ig = 1.f / (1.f + __expf(-gi));
    float fg = 1.f / (1.f + __expf(-gf));
    float og = 1.f / (1.f + __expf(-go));
    float gv = tanhf(gg);
    float cn = fg * cbuf[off] + ig * gv;
    cbuf[off] = cn;
    __stcg(&hdst[off], og * tanhf(cn));
}

// ---------------- persistent kernel ----------------
__global__ void __launch_bounds__(THREADS, 1)
lstm_persistent(const float* __restrict__ x,
                const float* __restrict__ wih0, const float* __restrict__ whh0,
                const float* __restrict__ bih0, const float* __restrict__ bhh0,
                const float* __restrict__ wih1, const float* __restrict__ whh1,
                const float* __restrict__ bih1, const float* __restrict__ bhh1,
                const float* __restrict__ lin_w, const float* __restrict__ lin_b,
                float* __restrict__ out)
{
    extern __shared__ float smemf[];
    const unsigned smem32 = (unsigned)__cvta_generic_to_shared(smemf);
    const unsigned hs32 = smem32;
    const unsigned ws32 = smem32 + SMEM_WS_OFF;
    const unsigned mb0 = smem32 + SMEM_MBAR_OFF, mb1 = mb0 + 8;
    float* Hs = smemf;
    const u64* Ws = (const u64*)((const char*)smemf + SMEM_WS_OFF);
    const int blk = blockIdx.x, tid = threadIdx.x;
    const int lane = tid & 31, wid = tid >> 5;
    const bool dmaT = (tid == 384);
    const bool comp = (wid < 12);

    // Tile map (both layers): sk = K-half, wg in 0..5; id -> bg (batch grp), cg (col grp)
    const int sk = (wid < 12) ? (wid / 6) : 0;
    const int wg = (wid < 12) ? (wid % 6) : 0;
    const int id = wg * 32 + lane;
    const int bg = id / 6, cg = id - bg * 6;     // bg 0..31, cg 0..5
    const int boff = bg * 4;

    // ---- one-time init ----
    {
        const int gi = blk * THREADS + tid, gs = NBLK * THREADS;
        for (int i = gi; i < 2 * Hq * Bq; i += gs) {
            ((float*)g_h0)[i] = 0.f;  ((float*)g_h1)[i] = 0.f;
        }
        for (int i = gi; i < Hq * Bq; i += gs) { g_c0[i] = 0.f; g_c1[i] = 0.f; }
        for (int g = gi; g < 4 * Hq; g += gs) {
            g_bias0[g] = bih0[g] + bhh0[g];
            g_bias1[g] = bih1[g] + bhh1[g];
        }
        const int NX = Bq * Tq * IN_DIM;
        for (int i = gi; i < NX; i += gs) {
            int b = i / (Tq * IN_DIM);
            int r = i - b * (Tq * IN_DIM);
            int t = r / IN_DIM, ii = r - t * IN_DIM;
            g_xT[(t * IN_DIM + ii) * Bq + b] = x[i];
        }
        for (int i = gi; i < Bq; i += gs) g_xT[Tq * IN_DIM * Bq + i] = 0.f;  // pad row
    }
    // ---- per-block duplicated-weight gather (chunked layout) ----
    if (blk < NB0) {
        const int u0 = blk * NU0;
        u64* wd = g_w0p + (size_t)blk * W0_SZ;
        for (int i = tid; i < Hq * 48; i += THREADS) {
            int kg = i / 48, c = i - kg * 48;
            int gate = c / 12, u = c - gate * 12;
            int unit = u0 + u; if (unit > Hq - 1) unit = Hq - 1;
            wd[(kg / KC) * W0_CH + (kg % KC) * 48 + c] =
                pack2(whh0[(size_t)(gate * Hq + unit) * Hq + kg]);
        }
        u64* wx = g_wxp + (size_t)blk * WX_SZ;
        for (int i = tid; i < 18 * 48; i += THREADS) {
            int kg = i / 48, c = i - kg * 48;
            int gate = c / 12, u = c - gate * 12;
            int unit = u0 + u; if (unit > Hq - 1) unit = Hq - 1;
            wx[i] = (kg < IN_DIM)
                  ? pack2(wih0[(size_t)(gate * Hq + unit) * IN_DIM + kg]) : 0ull;
        }
    } else {
        const int lb = blk - NB0, u0 = lb * NU1;
        u64* wi = g_w1i + (size_t)lb * W1_SZ;
        u64* wh = g_w1h + (size_t)lb * W1_SZ;
        for (int i = tid; i < Hq * 24; i += THREADS) {
            int kg = i / 24, c = i - kg * 24;
            int gate = c / 6, u = c - gate * 6;
            int unit = u0 + u; if (unit > Hq - 1) unit = Hq - 1;
            size_t dst = (kg / KC) * W1_CH + (kg % KC) * 24 + c;
            wi[dst] = pack2(wih1[(size_t)(gate * Hq + unit) * Hq + kg]);
            wh[dst] = pack2(whh1[(size_t)(gate * Hq + unit) * Hq + kg]);
        }
    }
    if (tid == 0) { mbar_init(mb0, 1); mbar_init(mb1, 1); }
    __syncthreads();
    grid_barrier();

    int ph0 = 0, ph1 = 0;

    if (blk < NB0) {
        // =================== LAYER 0: 9 chunks (8 h + 1 x) ===================
        const int u0 = blk * NU0;
        const u64* wd = g_w0p + (size_t)blk * W0_SZ;
        const u64* wx = g_wxp + (size_t)blk * WX_SZ;
        const int coff = cg * 8;

        #pragma unroll 1
        for (int t = 0; t <= Tq; ++t) {
            if (t < Tq) {
                const float* hprev = g_h0[(t + 1) & 1];
                const float* xrow = g_xT + (size_t)t * IN_DIM * Bq;
                if (dmaT) {   // prefetch chunks 0,1
                    mbar_expect(mb0, 32768 + 24576);
                    bulk_g2s(hs32, hprev, 32768, mb0);
                    bulk_g2s(ws32, wd, 24576, mb0);
                    mbar_expect(mb1, 32768 + 24576);
                    bulk_g2s(hs32 + 32768, hprev + KC * Bq, 32768, mb1);
                    bulk_g2s(ws32 + 24576, wd + W0_CH, 24576, mb1);
                }
                u64 acc[8][2];
                #pragma unroll
                for (int j = 0; j < 8; ++j) { acc[j][0] = 0ull; acc[j][1] = 0ull; }

                for (int c = 0; c < 9; ++c) {
                    if (comp) {
                        if (c & 1) { mbar_wait(mb1, ph1); ph1 ^= 1; }
                        else       { mbar_wait(mb0, ph0); ph0 ^= 1; }
                        const float* hp = Hs + (c & 1) * (KC * Bq) + boff;
                        const u64*   wp = Ws + (c & 1) * W0_CH + coff;
                        if (c < 8) l0_inner(hp, wp, sk ? 32 : 0, sk ? 64 : 32, acc);
                        else       l0_inner(hp, wp, sk ?  9 : 0, sk ? 18 :  9, acc);
                    }
                    __syncthreads();
                    if (dmaT && c + 2 < 9) {
                        unsigned mbx = (c & 1) ? mb1 : mb0;
                        unsigned hd = hs32 + (unsigned)(c & 1) * 32768;
                        unsigned wdd = ws32 + (unsigned)(c & 1) * 24576;
                        if (c + 2 < 8) {
                            mbar_expect(mbx, 32768 + 24576);
                            bulk_g2s(hd, hprev + (c + 2) * KC * Bq, 32768, mbx);
                            bulk_g2s(wdd, wd + (c + 2) * W0_CH, 24576, mbx);
                        } else {   // x chunk: 18 rows
                            mbar_expect(mbx, 9216 + 6912);
                            bulk_g2s(hd, xrow, 9216, mbx);
                            bulk_g2s(wdd, wx, 6912, mbx);
                        }
                    }
                }
                // ---- epilogue: split-K reduce + cell ----
                {
                    ulonglong2* G2 = (ulonglong2*)smemf;   // [sk][48][32]
                    if (comp) {
                        #pragma unroll
                        for (int j = 0; j < 8; ++j)
                            G2[sk * 1536 + (coff + j) * 32 + bg] =
                                make_ulonglong2(acc[j][0], acc[j][1]);
                    }
                    __syncthreads();
                    if (tid < 384) {
                        const float* Gf = smemf;
                        const int b = tid & 127, q = tid >> 7;   // q 0..2
                        #pragma unroll
                        for (int u = q; u < NU0; u += 3) {
                            int unit = u0 + u;
                            if (unit < Hq) {
                                float gi = Gf[(u       )*Bq+b] + Gf[6144+(u       )*Bq+b] + g_bias0[unit       ];
                                float gf = Gf[(u+  NU0)*Bq+b] + Gf[6144+(u+  NU0)*Bq+b] + g_bias0[unit+  Hq];
                                float gg = Gf[(u+2*NU0)*Bq+b] + Gf[6144+(u+2*NU0)*Bq+b] + g_bias0[unit+2*Hq];
                                float go = Gf[(u+3*NU0)*Bq+b] + Gf[6144+(u+3*NU0)*Bq+b] + g_bias0[unit+3*Hq];
                                cell(gi, gf, gg, go, g_c0, g_h0[t & 1], unit * Bq + b);
                            }
                        }
                    }
                    __syncthreads();
                }
            }
            grid_barrier();
        }
    } else {
        // =================== LAYER 1: 16 chunks (8 wi + 8 wh) =================
        const int lb = blk - NB0, u0 = lb * NU1;
        const u64* wi = g_w1i + (size_t)lb * W1_SZ;
        const u64* wh = g_w1h + (size_t)lb * W1_SZ;
        const int coff = cg * 4;

        #pragma unroll 1
        for (int t = 0; t <= Tq; ++t) {
            if (t >= 1) {
                const int s = t - 1;
                const float* h0s = g_h0[s & 1];
                const float* h1p = g_h1[(s + 1) & 1];
                if (dmaT) {
                    mbar_expect(mb0, 32768 + 12288);
                    bulk_g2s(hs32, h0s, 32768, mb0);
                    bulk_g2s(ws32, wi, 12288, mb0);
                    mbar_expect(mb1, 32768 + 12288);
                    bulk_g2s(hs32 + 32768, h0s + KC * Bq, 32768, mb1);
                    bulk_g2s(ws32 + 12288, wi + W1_CH, 12288, mb1);
                }
                u64 acc[4][2];
                #pragma unroll
                for (int j = 0; j < 4; ++j) { acc[j][0] = 0ull; acc[j][1] = 0ull; }

                for (int c = 0; c < 16; ++c) {
                    if (comp) {
                        if (c & 1) { mbar_wait(mb1, ph1); ph1 ^= 1; }
                        else       { mbar_wait(mb0, ph0); ph0 ^= 1; }
                        const float* hp = Hs + (c & 1) * (KC * Bq) + boff;
                        const u64*   wp = Ws + (c & 1) * W1_CH + coff;
                        l1_inner(hp, wp, sk ? 32 : 0, sk ? 64 : 32, acc);
                    }
                    __syncthreads();
                    if (dmaT && c + 2 < 16) {
                        int cn = c + 2;
                        unsigned mbx = (c & 1) ? mb1 : mb0;
                        unsigned hd = hs32 + (unsigned)(c & 1) * 32768;
                        unsigned wdd = ws32 + (unsigned)(c & 1) * 12288;
                        const float* hsrc = (cn < 8) ? (h0s + cn * KC * Bq)
                                                     : (h1p + (cn - 8) * KC * Bq);
                        const u64* wsrc = (cn < 8) ? (wi + cn * W1_CH)
                                                   : (wh + (cn - 8) * W1_CH);
                        mbar_expect(mbx, 32768 + 12288);
                        bulk_g2s(hd, hsrc, 32768, mbx);
                        bulk_g2s(wdd, wsrc, 12288, mbx);
                    }
                }
                // ---- epilogue ----
                {
                    ulonglong2* G2 = (ulonglong2*)smemf;   // [sk][24][32]
                    if (comp) {
                        #pragma unroll
                        for (int j = 0; j < 4; ++j)
                            G2[sk * 768 + (coff + j) * 32 + bg] =
                                make_ulonglong2(acc[j][0], acc[j][1]);
                    }
                    __syncthreads();
                    if (tid < 384) {
                        const float* Gf = smemf;
                        const int b = tid & 127, q = tid >> 7;
                        #pragma unroll
                        for (int u = q; u < NU1; u += 3) {
                            int unit = u0 + u;
                            if (unit < Hq) {
                                float gi = Gf[(u       )*Bq+b] + Gf[3072+(u       )*Bq+b] + g_bias1[unit       ];
                                float gf = Gf[(u+  NU1)*Bq+b] + Gf[3072+(u+  NU1)*Bq+b] + g_bias1[unit+  Hq];
                                float gg = Gf[(u+2*NU1)*Bq+b] + Gf[3072+(u+2*NU1)*Bq+b] + g_bias1[unit+2*Hq];
                                float go = Gf[(u+3*NU1)*Bq+b] + Gf[3072+(u+3*NU1)*Bq+b] + g_bias1[unit+3*Hq];
                                cell(gi, gf, gg, go, g_c1, g_h1[s & 1], unit * Bq + b);
                            }
                        }
                    }
                    __syncthreads();
                }
            }
            grid_barrier();
        }
    }

    // ---- final linear: out[b][o] = h1_last[:,b] . lin_w[o,:] + lin_b[o] ----
    if (blk < OUT_DIM && tid < Bq) {
        const int o = blk, b = tid;
        const float* h = g_h1[(Tq - 1) & 1];
        float a = __ldg(&lin_b[o]);
        #pragma unroll 8
        for (int k = 0; k < Hq; ++k)
            a += __ldcg(&h[k * Bq + b]) * __ldg(&lin_w[o * Hq + k]);
        out[b * OUT_DIM + o] = a;
    }
}

extern "C" void kernel_launch(void* const* d_in, const int* in_sizes, int n_in,
                              void* d_out, int out_size)
{
    const float* x     = (const float*)d_in[0];
    const float* wih0  = (const float*)d_in[1];
    const float* whh0  = (const float*)d_in[2];
    const float* bih0  = (const float*)d_in[3];
    const float* bhh0  = (const float*)d_in[4];
    const float* wih1  = (const float*)d_in[5];
    const float* whh1  = (const float*)d_in[6];
    const float* bih1  = (const float*)d_in[7];
    const float* bhh1  = (const float*)d_in[8];
    const float* lin_w = (const float*)d_in[9];
    const float* lin_b = (const float*)d_in[10];
    float* out = (float*)d_out;

    cudaFuncSetAttribute(lstm_persistent,
                         cudaFuncAttributeMaxDynamicSharedMemorySize, SMEM_BYTES);

    lstm_persistent<<<NBLK, THREADS, SMEM_BYTES>>>(
        x, wih0, whh0, bih0, bhh0, wih1, whh1, bih1, bhh1, lin_w, lin_b, out);
}